// round 3
// baseline (speedup 1.0000x reference)
#include <cuda_runtime.h>
#include <cstdint>

#define NBLK 1184   // 148 SMs * 8 CTAs
#define NTHR 256

__device__ float g_psum[NBLK];
__device__ int   g_pcnt[NBLK];

__device__ __forceinline__ void bce_elem(float p, int t, float& s, int& c) {
    // t==1: -log(p); t==0: -log(1-p); t==2: 0
    float v = (t == 1) ? (-__logf(p)) : ((t == 0) ? (-__logf(1.0f - p)) : 0.0f);
    s += v;
    c += (t < 2) ? 1 : 0;
}

__global__ __launch_bounds__(NTHR) void bce_partial_kernel(
    const float* __restrict__ prob,
    const int* __restrict__ tgt,
    int n4)   // number of 4-element groups
{
    const float4* p4 = reinterpret_cast<const float4*>(prob);
    const int4*   t4 = reinterpret_cast<const int4*>(tgt);

    float s = 0.0f;
    int   c = 0;

    int stride = gridDim.x * blockDim.x;
    for (int i = blockIdx.x * blockDim.x + threadIdx.x; i < n4; i += stride) {
        float4 p = p4[i];
        int4   t = t4[i];
        bce_elem(p.x, t.x, s, c);
        bce_elem(p.y, t.y, s, c);
        bce_elem(p.z, t.z, s, c);
        bce_elem(p.w, t.w, s, c);
    }

    // Block reduction
    __shared__ float ss[NTHR];
    __shared__ int   sc[NTHR];
    int tid = threadIdx.x;
    ss[tid] = s;
    sc[tid] = c;
    __syncthreads();
    #pragma unroll
    for (int off = NTHR / 2; off >= 32; off >>= 1) {
        if (tid < off) {
            ss[tid] += ss[tid + off];
            sc[tid] += sc[tid + off];
        }
        __syncthreads();
    }
    if (tid < 32) {
        float ws = ss[tid];
        int   wc = sc[tid];
        #pragma unroll
        for (int off = 16; off > 0; off >>= 1) {
            ws += __shfl_down_sync(0xFFFFFFFFu, ws, off);
            wc += __shfl_down_sync(0xFFFFFFFFu, wc, off);
        }
        if (tid == 0) {
            g_psum[blockIdx.x] = ws;
            g_pcnt[blockIdx.x] = wc;
        }
    }
}

__global__ __launch_bounds__(1024) void bce_final_kernel(float* __restrict__ out) {
    __shared__ float ss[1024];
    __shared__ int   sc[1024];
    int tid = threadIdx.x;
    float s = 0.0f;
    int   c = 0;
    for (int i = tid; i < NBLK; i += 1024) {
        s += g_psum[i];
        c += g_pcnt[i];
    }
    ss[tid] = s;
    sc[tid] = c;
    __syncthreads();
    #pragma unroll
    for (int off = 512; off >= 32; off >>= 1) {
        if (tid < off) {
            ss[tid] += ss[tid + off];
            sc[tid] += sc[tid + off];
        }
        __syncthreads();
    }
    if (tid < 32) {
        float ws = ss[tid];
        int   wc = sc[tid];
        #pragma unroll
        for (int off = 16; off > 0; off >>= 1) {
            ws += __shfl_down_sync(0xFFFFFFFFu, ws, off);
            wc += __shfl_down_sync(0xFFFFFFFFu, wc, off);
        }
        if (tid == 0) {
            out[0] = ws / (float)wc;
        }
    }
}

extern "C" void kernel_launch(void* const* d_in, const int* in_sizes, int n_in,
                              void* d_out, int out_size) {
    const float* prob = (const float*)d_in[0];
    const int*   tgt  = (const int*)d_in[1];
    float*       out  = (float*)d_out;

    int n  = in_sizes[0];   // 40,960,000 (divisible by 4)
    int n4 = n / 4;

    bce_partial_kernel<<<NBLK, NTHR>>>(prob, tgt, n4);
    bce_final_kernel<<<1, 1024>>>(out);
}

// round 6
// speedup vs baseline: 1.0419x; 1.0419x over previous
#include <cuda_runtime.h>
#include <cstdint>

#define NBLK 1184   // 148 SMs * 8 CTAs
#define NTHR 256

__device__ float g_psum[NBLK];
__device__ int   g_pcnt[NBLK];
__device__ int   g_ticket;   // zero-initialized; reset to 0 by last block each run

__device__ __forceinline__ void bce_elem(float p, int t, float& s, int& c) {
    // t==1: -log(p); t==0: -log(1-p); t==2: 0
    float v = (t == 1) ? (-__logf(p)) : ((t == 0) ? (-__logf(1.0f - p)) : 0.0f);
    s += v;
    c += (t < 2) ? 1 : 0;
}

__global__ __launch_bounds__(NTHR) void bce_fused_kernel(
    const float* __restrict__ prob,
    const int* __restrict__ tgt,
    int n8,          // number of 8-element groups
    float* __restrict__ out)
{
    const float4* p4 = reinterpret_cast<const float4*>(prob);
    const int4*   t4 = reinterpret_cast<const int4*>(tgt);

    float s = 0.0f;
    int   c = 0;

    int stride = gridDim.x * blockDim.x;
    for (int i = blockIdx.x * blockDim.x + threadIdx.x; i < n8; i += stride) {
        // Front-batch all 4 vector loads for MLP
        float4 pa = __ldcs(&p4[2 * i]);
        float4 pb = __ldcs(&p4[2 * i + 1]);
        int4   ta = __ldcs(&t4[2 * i]);
        int4   tb = __ldcs(&t4[2 * i + 1]);
        bce_elem(pa.x, ta.x, s, c);
        bce_elem(pa.y, ta.y, s, c);
        bce_elem(pa.z, ta.z, s, c);
        bce_elem(pa.w, ta.w, s, c);
        bce_elem(pb.x, tb.x, s, c);
        bce_elem(pb.y, tb.y, s, c);
        bce_elem(pb.z, tb.z, s, c);
        bce_elem(pb.w, tb.w, s, c);
    }

    // Block reduction
    __shared__ float ss[NTHR];
    __shared__ int   sc[NTHR];
    __shared__ bool  is_last;
    int tid = threadIdx.x;
    ss[tid] = s;
    sc[tid] = c;
    __syncthreads();
    #pragma unroll
    for (int off = NTHR / 2; off >= 32; off >>= 1) {
        if (tid < off) {
            ss[tid] += ss[tid + off];
            sc[tid] += sc[tid + off];
        }
        __syncthreads();
    }
    if (tid < 32) {
        float ws = ss[tid];
        int   wc = sc[tid];
        #pragma unroll
        for (int off = 16; off > 0; off >>= 1) {
            ws += __shfl_down_sync(0xFFFFFFFFu, ws, off);
            wc += __shfl_down_sync(0xFFFFFFFFu, wc, off);
        }
        if (tid == 0) {
            g_psum[blockIdx.x] = ws;
            g_pcnt[blockIdx.x] = wc;
            __threadfence();
            int ticket = atomicAdd(&g_ticket, 1);
            is_last = (ticket == gridDim.x - 1);
        }
    }
    __syncthreads();

    // Last block to finish performs the final reduction (deterministic order)
    if (is_last) {
        float fs = 0.0f;
        int   fc = 0;
        for (int i = tid; i < NBLK; i += NTHR) {
            fs += g_psum[i];
            fc += g_pcnt[i];
        }
        ss[tid] = fs;
        sc[tid] = fc;
        __syncthreads();
        #pragma unroll
        for (int off = NTHR / 2; off >= 32; off >>= 1) {
            if (tid < off) {
                ss[tid] += ss[tid + off];
                sc[tid] += sc[tid + off];
            }
            __syncthreads();
        }
        if (tid < 32) {
            float ws = ss[tid];
            int   wc = sc[tid];
            #pragma unroll
            for (int off = 16; off > 0; off >>= 1) {
                ws += __shfl_down_sync(0xFFFFFFFFu, ws, off);
                wc += __shfl_down_sync(0xFFFFFFFFu, wc, off);
            }
            if (tid == 0) {
                out[0] = ws / (float)wc;
                atomicExch(&g_ticket, 0);   // reset for next graph replay
            }
        }
    }
}

extern "C" void kernel_launch(void* const* d_in, const int* in_sizes, int n_in,
                              void* d_out, int out_size) {
    const float* prob = (const float*)d_in[0];
    const int*   tgt  = (const int*)d_in[1];
    float*       out  = (float*)d_out;

    int n  = in_sizes[0];   // 40,960,000 (divisible by 8)
    int n8 = n / 8;

    bce_fused_kernel<<<NBLK, NTHR>>>(prob, tgt, n8, out);
}